// round 13
// baseline (speedup 1.0000x reference)
#include <cuda_runtime.h>
#include <cuda_fp16.h>
#include <cstdint>

#define B_DIM 8
#define R_DIM 128
#define H_DIM 4096
#define W_DIM 4096
#define KSPLIT 16

// Scratch (device globals: allocation-free per harness rules)
__device__ float  g_part[KSPLIT * B_DIM * R_DIM * R_DIM]; // 8 MB partial Gram
__device__ float  g_Q[B_DIM * R_DIM * R_DIM];             // 512KB Q = 2g*C^-1
__device__ __half g_Nh[B_DIM * R_DIM * W_DIM];            // 8 MB N hi (fp16)
__device__ __half g_Nl[B_DIM * R_DIM * W_DIM];            // 8 MB N lo (fp16)
__device__ int    g_qflag[B_DIM];                         // Q-ready flags (zero-init)

// ---------------------------------------------------------------------------
// K0: split N (fp32) into fp16 hi/lo pair, elementwise.
// ---------------------------------------------------------------------------
__global__ void __launch_bounds__(256) k0_split(const float* __restrict__ Nn) {
    size_t e = ((size_t)blockIdx.x * 256 + threadIdx.x) * 4;
    float4 v = *(const float4*)(Nn + e);
    __half h0 = __float2half_rn(v.x), h1 = __float2half_rn(v.y);
    __half h2 = __float2half_rn(v.z), h3 = __float2half_rn(v.w);
    __half l0 = __float2half_rn(v.x - __half2float(h0));
    __half l1 = __float2half_rn(v.y - __half2float(h1));
    __half l2 = __float2half_rn(v.z - __half2float(h2));
    __half l3 = __float2half_rn(v.w - __half2float(h3));
    __half2 hh0 = __halves2half2(h0, h1), hh1 = __halves2half2(h2, h3);
    __half2 ll0 = __halves2half2(l0, l1), ll1 = __halves2half2(l2, l3);
    *(uint2*)(g_Nh + e) = make_uint2(*(uint32_t*)&hh0, *(uint32_t*)&hh1);
    *(uint2*)(g_Nl + e) = make_uint2(*(uint32_t*)&ll0, *(uint32_t*)&ll1);
}

// ---------------------------------------------------------------------------
// K1: partial Gram  part[ks][b][r][s] = sum_{w in split} N[r][w]*N[s][w]
// ---------------------------------------------------------------------------
__global__ void __launch_bounds__(256) k1_gram(const float* __restrict__ N) {
    __shared__ float Ns[32][132];
    int ks = blockIdx.x, b = blockIdx.y;
    int tid = threadIdx.x;
    int tx = tid & 15, ty = tid >> 4;
    const float* Nb = N + (size_t)b * R_DIM * W_DIM;

    float acc[8][8];
#pragma unroll
    for (int i = 0; i < 8; i++)
#pragma unroll
        for (int j = 0; j < 8; j++) acc[i][j] = 0.f;

    int k0 = ks * (W_DIM / KSPLIT);
    for (int kk = k0; kk < k0 + W_DIM / KSPLIT; kk += 32) {
#pragma unroll
        for (int i = 0; i < 4; i++) {
            int u = tid + i * 256;
            int row = u >> 3, j = u & 7;
            float4 v = *(const float4*)(Nb + (size_t)row * W_DIM + kk + j * 4);
            Ns[j * 4 + 0][row] = v.x;
            Ns[j * 4 + 1][row] = v.y;
            Ns[j * 4 + 2][row] = v.z;
            Ns[j * 4 + 3][row] = v.w;
        }
        __syncthreads();
#pragma unroll
        for (int k = 0; k < 32; k++) {
            float4 a0 = *(const float4*)&Ns[k][ty * 8];
            float4 a1 = *(const float4*)&Ns[k][ty * 8 + 4];
            float4 b0 = *(const float4*)&Ns[k][tx * 8];
            float4 b1 = *(const float4*)&Ns[k][tx * 8 + 4];
            float av[8] = {a0.x, a0.y, a0.z, a0.w, a1.x, a1.y, a1.z, a1.w};
            float bv[8] = {b0.x, b0.y, b0.z, b0.w, b1.x, b1.y, b1.z, b1.w};
#pragma unroll
            for (int i = 0; i < 8; i++)
#pragma unroll
                for (int j = 0; j < 8; j++)
                    acc[i][j] = fmaf(av[i], bv[j], acc[i][j]);
        }
        __syncthreads();
    }
    float* P = g_part + (size_t)(ks * B_DIM + b) * 16384;
#pragma unroll
    for (int i = 0; i < 8; i++)
#pragma unroll
        for (int j = 0; j < 8; j += 4)
            *(float4*)&P[(ty * 8 + i) * 128 + tx * 8 + j] =
                make_float4(acc[i][j], acc[i][j + 1], acc[i][j + 2], acc[i][j + 3]);
}

// ---------------------------------------------------------------------------
// K2: C = alpha*I + 2*gamma*G; register-resident Gauss-Jordan inverse.
// Writes Q = 2*gamma * C^-1, then raises g_qflag[b].
// ---------------------------------------------------------------------------
__global__ void __launch_bounds__(1024, 1) k2_inv(const float* __restrict__ alpha,
                                                  const float* __restrict__ gamma) {
    __shared__ float s_rowk[2][128];
    __shared__ float s_colk[2][128];
    __shared__ float s_invp[2];

    int b = blockIdx.x;
    int t = threadIdx.x;
    int i  = t >> 3;
    int jc = (t & 7) << 4;
    float a  = alpha[b];
    float g2 = 2.0f * gamma[b];

    float M[16];
#pragma unroll
    for (int q = 0; q < 16; q++) {
        int e = i * 128 + jc + q;
        float s = 0.f;
#pragma unroll
        for (int p = 0; p < KSPLIT; p++)
            s += g_part[((size_t)(p * B_DIM + b)) * 16384 + e];
        M[q] = g2 * s + ((jc + q) == i ? a : 0.f);
    }
    if (i == 0) {
#pragma unroll
        for (int q = 0; q < 16; q++) s_rowk[0][jc + q] = M[q];
        if (jc == 0) s_invp[0] = 1.0f / M[0];
    }
    if (jc == 0) s_colk[0][i] = M[0];
    __syncthreads();

    for (int k = 0; k < 128; k++) {
        int par = k & 1;
        float ip = s_invp[par];
        if (i == k) {
#pragma unroll
            for (int q = 0; q < 16; q++) M[q] *= ip;
            if (k >= jc && k < jc + 16) M[k - jc] = ip;
        } else {
            float c = s_colk[par][i] * ip;
#pragma unroll
            for (int q = 0; q < 16; q++)
                M[q] = fmaf(-c, s_rowk[par][jc + q], M[q]);
            if (k >= jc && k < jc + 16) M[k - jc] = -c;
        }
        int kn = k + 1;
        if (kn < 128) {
            int pn = kn & 1;
            if (i == kn) {
#pragma unroll
                for (int q = 0; q < 16; q++) s_rowk[pn][jc + q] = M[q];
                if (kn >= jc && kn < jc + 16) s_invp[pn] = 1.0f / M[kn - jc];
            }
            if (kn >= jc && kn < jc + 16) s_colk[pn][i] = M[kn - jc];
        }
        __syncthreads();
    }

    float* Qo = g_Q + (size_t)b * 16384;
#pragma unroll
    for (int q = 0; q < 16; q++)
        Qo[i * 128 + jc + q] = g2 * M[q];

    __syncthreads();
    if (t == 0) {
        __threadfence();
        atomicExch(&g_qflag[b], 1);
    }
}

// ---------------------------------------------------------------------------
// K4: fused  AN = A @ N^T  (fp16 2-way split, 3x HMMA, fp32 acc)
//            out = AN @ Q  (fp32 epilogue through smem; spins on g_qflag[b])
// ---------------------------------------------------------------------------
#define BM 256
#define BK 32
#define NTHREADS 512
#define RS 40                          // halves per smem row (80B, 16B-aligned)
#define ASTG (512 * RS)                // halves per A stage (256 rows hi + lo)
#define A_LO_B (256 * RS * 2)          // byte offset of A-lo inside stage
#define BOFF (2 * ASTG)                // halves: start of B region
#define BSTG (256 * RS)                // halves per B stage (128 rows hi + lo)
#define B_LO_B (128 * RS * 2)          // byte offset of B-lo inside stage
#define K4_SMEM ((2 * ASTG + 3 * BSTG) * 2)   // 143360 bytes (>= epilogue 135168)

__device__ __forceinline__ uint32_t smem_u32(const void* p) {
    return (uint32_t)__cvta_generic_to_shared(p);
}
__device__ __forceinline__ void cp_async16(uint32_t saddr, const void* g) {
    asm volatile("cp.async.cg.shared.global [%0], [%1], 16;" :: "r"(saddr), "l"(g) : "memory");
}
__device__ __forceinline__ void ldsm_x4(uint32_t addr, uint32_t& r0, uint32_t& r1,
                                        uint32_t& r2, uint32_t& r3) {
    asm volatile("ldmatrix.sync.aligned.m8n8.x4.shared.b16 {%0,%1,%2,%3}, [%4];"
                 : "=r"(r0), "=r"(r1), "=r"(r2), "=r"(r3) : "r"(addr));
}
__device__ __forceinline__ void mma_f16(float* d, const uint32_t* a, const uint32_t* b) {
    asm volatile(
        "mma.sync.aligned.m16n8k16.row.col.f32.f16.f16.f32 "
        "{%0,%1,%2,%3}, {%4,%5,%6,%7}, {%8,%9}, {%0,%1,%2,%3};"
        : "+f"(d[0]), "+f"(d[1]), "+f"(d[2]), "+f"(d[3])
        : "r"(a[0]), "r"(a[1]), "r"(a[2]), "r"(a[3]),
          "r"(b[0]), "r"(b[1]));
}
__device__ __forceinline__ uint32_t pack_hi(float x, float y) {
    __half2 h = __halves2half2(__float2half_rn(x), __float2half_rn(y));
    return *(uint32_t*)&h;
}
__device__ __forceinline__ uint32_t pack_lo(float x, float y) {
    __half hx = __float2half_rn(x), hy = __float2half_rn(y);
    __half2 l = __halves2half2(__float2half_rn(x - __half2float(hx)),
                               __float2half_rn(y - __half2float(hy)));
    return *(uint32_t*)&l;
}

__global__ void __launch_bounds__(NTHREADS, 1) k4_fused(const float* __restrict__ A,
                                                        float* __restrict__ O) {
    extern __shared__ __half smh[];
    uint32_t sb = smem_u32(smh);
    int b  = blockIdx.y;
    int m0 = blockIdx.x * BM;
    int tid = threadIdx.x;
    int lane = tid & 31, wid = tid >> 5;
    int wm = wid & 3;        // 4 warps in M -> 64 rows each
    int wn = wid >> 2;       // 4 warps in N -> 32 cols each

    const float*  Ab  = A + (size_t)b * H_DIM * W_DIM;
    const __half* Bhg = g_Nh + (size_t)b * R_DIM * W_DIM;
    const __half* Blg = g_Nl + (size_t)b * R_DIM * W_DIM;

    float acc[4][4][4];
#pragma unroll
    for (int mt = 0; mt < 4; mt++)
#pragma unroll
        for (int nt = 0; nt < 4; nt++)
#pragma unroll
            for (int r = 0; r < 4; r++) acc[mt][nt][r] = 0.f;

    float4 a4[4];
    int brow = tid >> 2, bcol = tid & 3;

    auto ldg_A = [&](int kk) {
#pragma unroll
        for (int i = 0; i < 4; i++) {
            int v = tid + i * NTHREADS;
            int row = v >> 3, kc = v & 7;
            a4[i] = *(const float4*)(Ab + (size_t)(m0 + row) * W_DIM + kk + kc * 4);
        }
    };
    auto cpb = [&](int st, int kk) {
        uint32_t bbase = sb + (BOFF + st * BSTG) * 2;
        uint32_t off = (uint32_t)(brow * RS + bcol * 8) * 2;
        cp_async16(bbase + off,          Bhg + (size_t)brow * W_DIM + kk + bcol * 8);
        cp_async16(bbase + B_LO_B + off, Blg + (size_t)brow * W_DIM + kk + bcol * 8);
        asm volatile("cp.async.commit_group;" ::: "memory");
    };
    auto sts_A = [&](int st) {
        uint32_t abase = sb + st * (ASTG * 2);
#pragma unroll
        for (int i = 0; i < 4; i += 2) {
            int v0i = tid + i * NTHREADS;
            int v1i = tid + (i + 1) * NTHREADS;
            int r0 = v0i >> 3, c0 = v0i & 7;
            int r1 = v1i >> 3, c1 = v1i & 7;
            uint32_t h0 = pack_hi(a4[i].x, a4[i].y),   h1 = pack_hi(a4[i].z, a4[i].w);
            uint32_t l0 = pack_lo(a4[i].x, a4[i].y),   l1 = pack_lo(a4[i].z, a4[i].w);
            uint32_t h2 = pack_hi(a4[i+1].x, a4[i+1].y), h3 = pack_hi(a4[i+1].z, a4[i+1].w);
            uint32_t l2 = pack_lo(a4[i+1].x, a4[i+1].y), l3 = pack_lo(a4[i+1].z, a4[i+1].w);
            uint32_t o0 = (uint32_t)(r0 * RS + c0 * 4) * 2;
            uint32_t o1 = (uint32_t)(r1 * RS + c1 * 4) * 2;
            asm volatile("st.shared.v2.b32 [%0], {%1,%2};"
                         :: "r"(abase + o0), "r"(h0), "r"(h1) : "memory");
            asm volatile("st.shared.v2.b32 [%0], {%1,%2};"
                         :: "r"(abase + A_LO_B + o0), "r"(l0), "r"(l1) : "memory");
            asm volatile("st.shared.v2.b32 [%0], {%1,%2};"
                         :: "r"(abase + o1), "r"(h2), "r"(h3) : "memory");
            asm volatile("st.shared.v2.b32 [%0], {%1,%2};"
                         :: "r"(abase + A_LO_B + o1), "r"(l2), "r"(l3) : "memory");
        }
    };

    ldg_A(0);
    cpb(0, 0);
    cpb(1, BK);

    const int KITERS = W_DIM / BK; // 128
    for (int kb = 0; kb < KITERS; kb++) {
        sts_A(kb & 1);
        if (kb + 1 < KITERS)
            asm volatile("cp.async.wait_group 1;" ::: "memory");
        else
            asm volatile("cp.async.wait_group 0;" ::: "memory");
        __syncthreads();
        if (kb + 1 < KITERS) ldg_A((kb + 1) * BK);
        if (kb + 2 < KITERS) cpb((kb + 2) % 3, (kb + 2) * BK);

        uint32_t abase = sb + (kb & 1) * (ASTG * 2);
        uint32_t bbase = sb + (BOFF + (kb % 3) * BSTG) * 2;

#pragma unroll
        for (int ks = 0; ks < 2; ks++) {
            uint32_t bhi[4][2], blo[4][2];
            int idx = lane >> 3;
            int kboff = ks * 32 + (idx & 1) * 16;
#pragma unroll
            for (int h = 0; h < 2; h++) {
                int nrow = wn * 32 + h * 16 + (idx >> 1) * 8 + (lane & 7);
                uint32_t r0, r1, r2, r3;
                ldsm_x4(bbase + nrow * (RS * 2) + kboff, r0, r1, r2, r3);
                bhi[2 * h][0] = r0; bhi[2 * h][1] = r1;
                bhi[2 * h + 1][0] = r2; bhi[2 * h + 1][1] = r3;
                ldsm_x4(bbase + B_LO_B + nrow * (RS * 2) + kboff, r0, r1, r2, r3);
                blo[2 * h][0] = r0; blo[2 * h][1] = r1;
                blo[2 * h + 1][0] = r2; blo[2 * h + 1][1] = r3;
            }
            int karow = ks * 32 + (lane >> 4) * 16;
#pragma unroll
            for (int mt = 0; mt < 4; mt++) {
                int arow = wm * 64 + mt * 16 + (lane & 15);
                uint32_t ah[4], al[4];
                ldsm_x4(abase + arow * (RS * 2) + karow, ah[0], ah[1], ah[2], ah[3]);
                ldsm_x4(abase + A_LO_B + arow * (RS * 2) + karow, al[0], al[1], al[2], al[3]);
#pragma unroll
                for (int nt = 0; nt < 4; nt++) mma_f16(acc[mt][nt], al, bhi[nt]);
#pragma unroll
                for (int nt = 0; nt < 4; nt++) mma_f16(acc[mt][nt], ah, blo[nt]);
#pragma unroll
                for (int nt = 0; nt < 4; nt++) mma_f16(acc[mt][nt], ah, bhi[nt]);
            }
        }
    }

    // ===== fused epilogue: out = acc @ Q (fp32), staged through smem =====
    if (tid == 0) {
        while (((volatile int*)g_qflag)[b] == 0) __nanosleep(64);
    }
    __syncthreads();
    __threadfence();

    float* Qs  = (float*)smh;              // [128][132]
    float* ANt = (float*)smh + 128 * 132;  // [128][132]  ANt[r][h_local]
    const float* Qb = g_Q + (size_t)b * 16384;
    for (int e = tid; e < 4096; e += NTHREADS) {
        int r = e >> 5, c4 = e & 31;
        float4 v = *(const float4*)(Qb + r * 128 + c4 * 4);
        *(float4*)(Qs + r * 132 + c4 * 4) = v;
    }

    int th = tid >> 4;   // 0..31 -> 4 h-rows each
    int ts = tid & 15;   // 0..15 -> 8 s-cols each
#pragma unroll
    for (int half = 0; half < 2; half++) {
        __syncthreads();
        if ((wm >> 1) == half) {
            int wml = wm & 1;
#pragma unroll
            for (int mt = 0; mt < 4; mt++)
#pragma unroll
                for (int nt = 0; nt < 4; nt++) {
                    int h = wml * 64 + mt * 16 + (lane >> 2);
                    int c = wn * 32 + nt * 8 + (lane & 3) * 2;
                    ANt[c * 132 + h]           = acc[mt][nt][0];
                    ANt[(c + 1) * 132 + h]     = acc[mt][nt][1];
                    ANt[c * 132 + h + 8]       = acc[mt][nt][2];
                    ANt[(c + 1) * 132 + h + 8] = acc[mt][nt][3];
                }
        }
        __syncthreads();

        float outr[4][8];
#pragma unroll
        for (int i = 0; i < 4; i++)
#pragma unroll
            for (int j = 0; j < 8; j++) outr[i][j] = 0.f;

        for (int r = 0; r < 128; r++) {
            float4 av4 = *(const float4*)(ANt + r * 132 + th * 4);
            float4 q0  = *(const float4*)(Qs  + r * 132 + ts * 8);
            float4 q1  = *(const float4*)(Qs  + r * 132 + ts * 8 + 4);
            float av[4] = {av4.x, av4.y, av4.z, av4.w};
            float qv[8] = {q0.x, q0.y, q0.z, q0.w, q1.x, q1.y, q1.z, q1.w};
#pragma unroll
            for (int i = 0; i < 4; i++)
#pragma unroll
                for (int j = 0; j < 8; j++)
                    outr[i][j] = fmaf(av[i], qv[j], outr[i][j]);
        }

        float* Ob = O + ((size_t)b * H_DIM + m0 + half * 128 + th * 4) * R_DIM + ts * 8;
#pragma unroll
        for (int i = 0; i < 4; i++) {
            *(float4*)(Ob + (size_t)i * R_DIM)     =
                make_float4(outr[i][0], outr[i][1], outr[i][2], outr[i][3]);
            *(float4*)(Ob + (size_t)i * R_DIM + 4) =
                make_float4(outr[i][4], outr[i][5], outr[i][6], outr[i][7]);
        }
    }
}

// ---------------------------------------------------------------------------
// Fork/join stream resources, created once at load.
// ---------------------------------------------------------------------------
namespace {
struct AuxStreams {
    cudaStream_t s2 = nullptr;
    cudaEvent_t  evA = nullptr, evB = nullptr;
    bool ok = false;
    AuxStreams() {
        ok = (cudaStreamCreateWithFlags(&s2, cudaStreamNonBlocking) == cudaSuccess) &&
             (cudaEventCreateWithFlags(&evA, cudaEventDisableTiming) == cudaSuccess) &&
             (cudaEventCreateWithFlags(&evB, cudaEventDisableTiming) == cudaSuccess);
    }
};
AuxStreams g_aux;
}

extern "C" void kernel_launch(void* const* d_in, const int* in_sizes, int n_in,
                              void* d_out, int out_size) {
    (void)in_sizes; (void)n_in; (void)out_size;
    const float* N     = (const float*)d_in[0];
    const float* A     = (const float*)d_in[1];
    const float* alpha = (const float*)d_in[2];
    const float* gamma = (const float*)d_in[3];
    float* out = (float*)d_out;

    cudaFuncSetAttribute(k4_fused, cudaFuncAttributeMaxDynamicSharedMemorySize, K4_SMEM);

    dim3 g1(KSPLIT, B_DIM);
    if (g_aux.ok) {
        // fork: Gram + inverse run concurrently; k4's epilogue spins on g_qflag.
        cudaEventRecord(g_aux.evA, 0);
        cudaStreamWaitEvent(g_aux.s2, g_aux.evA, 0);
        k1_gram<<<g1, 256, 0, g_aux.s2>>>(N);
        k2_inv<<<B_DIM, 1024, 0, g_aux.s2>>>(alpha, gamma);
    } else {
        k1_gram<<<g1, 256>>>(N);
        k2_inv<<<B_DIM, 1024>>>(alpha, gamma);
    }

    k0_split<<<(B_DIM * R_DIM * W_DIM) / 1024, 256>>>(N);
    dim3 g4(H_DIM / BM, B_DIM);   // 16 x 8 = 128 CTAs, one wave
    k4_fused<<<g4, NTHREADS, K4_SMEM>>>(A, out);

    if (g_aux.ok) {
        // join s2 back into the capture stream AFTER k4 is enqueued: k4 does
        // not depend on k2 in the graph (concurrency preserved); capture ends
        // with all forked work joined.
        cudaEventRecord(g_aux.evB, g_aux.s2);
        cudaStreamWaitEvent(0, g_aux.evB, 0);
    }
}

// round 14
// speedup vs baseline: 1.0740x; 1.0740x over previous
#include <cuda_runtime.h>
#include <cuda_fp16.h>
#include <cstdint>

#define B_DIM 8
#define R_DIM 128
#define H_DIM 4096
#define W_DIM 4096
#define KSPLIT 16
#define QSCALE 4096.0f

// Scratch (device globals: allocation-free per harness rules)
__device__ float  g_part[KSPLIT * B_DIM * R_DIM * R_DIM]; // 8 MB partial Gram
__device__ __half g_Qh[B_DIM * R_DIM * R_DIM];            // Q*4096 hi (fp16)
__device__ __half g_Ql[B_DIM * R_DIM * R_DIM];            // Q*4096 lo (fp16)
__device__ __half g_Nh[B_DIM * R_DIM * W_DIM];            // 8 MB N hi (fp16)
__device__ __half g_Nl[B_DIM * R_DIM * W_DIM];            // 8 MB N lo (fp16)
__device__ int    g_qflag[B_DIM];                         // Q-ready flags (zero-init)

// ---------------------------------------------------------------------------
// K0: split N (fp32) into fp16 hi/lo pair, elementwise.
// ---------------------------------------------------------------------------
__global__ void __launch_bounds__(256) k0_split(const float* __restrict__ Nn) {
    size_t e = ((size_t)blockIdx.x * 256 + threadIdx.x) * 4;
    float4 v = *(const float4*)(Nn + e);
    __half h0 = __float2half_rn(v.x), h1 = __float2half_rn(v.y);
    __half h2 = __float2half_rn(v.z), h3 = __float2half_rn(v.w);
    __half l0 = __float2half_rn(v.x - __half2float(h0));
    __half l1 = __float2half_rn(v.y - __half2float(h1));
    __half l2 = __float2half_rn(v.z - __half2float(h2));
    __half l3 = __float2half_rn(v.w - __half2float(h3));
    __half2 hh0 = __halves2half2(h0, h1), hh1 = __halves2half2(h2, h3);
    __half2 ll0 = __halves2half2(l0, l1), ll1 = __halves2half2(l2, l3);
    *(uint2*)(g_Nh + e) = make_uint2(*(uint32_t*)&hh0, *(uint32_t*)&hh1);
    *(uint2*)(g_Nl + e) = make_uint2(*(uint32_t*)&ll0, *(uint32_t*)&ll1);
}

// ---------------------------------------------------------------------------
// K1: partial Gram  part[ks][b][r][s] = sum_{w in split} N[r][w]*N[s][w]
// ---------------------------------------------------------------------------
__global__ void __launch_bounds__(256) k1_gram(const float* __restrict__ N) {
    __shared__ float Ns[32][132];
    int ks = blockIdx.x, b = blockIdx.y;
    int tid = threadIdx.x;
    int tx = tid & 15, ty = tid >> 4;
    const float* Nb = N + (size_t)b * R_DIM * W_DIM;

    float acc[8][8];
#pragma unroll
    for (int i = 0; i < 8; i++)
#pragma unroll
        for (int j = 0; j < 8; j++) acc[i][j] = 0.f;

    int k0 = ks * (W_DIM / KSPLIT);
    for (int kk = k0; kk < k0 + W_DIM / KSPLIT; kk += 32) {
#pragma unroll
        for (int i = 0; i < 4; i++) {
            int u = tid + i * 256;
            int row = u >> 3, j = u & 7;
            float4 v = *(const float4*)(Nb + (size_t)row * W_DIM + kk + j * 4);
            Ns[j * 4 + 0][row] = v.x;
            Ns[j * 4 + 1][row] = v.y;
            Ns[j * 4 + 2][row] = v.z;
            Ns[j * 4 + 3][row] = v.w;
        }
        __syncthreads();
#pragma unroll
        for (int k = 0; k < 32; k++) {
            float4 a0 = *(const float4*)&Ns[k][ty * 8];
            float4 a1 = *(const float4*)&Ns[k][ty * 8 + 4];
            float4 b0 = *(const float4*)&Ns[k][tx * 8];
            float4 b1 = *(const float4*)&Ns[k][tx * 8 + 4];
            float av[8] = {a0.x, a0.y, a0.z, a0.w, a1.x, a1.y, a1.z, a1.w};
            float bv[8] = {b0.x, b0.y, b0.z, b0.w, b1.x, b1.y, b1.z, b1.w};
#pragma unroll
            for (int i = 0; i < 8; i++)
#pragma unroll
                for (int j = 0; j < 8; j++)
                    acc[i][j] = fmaf(av[i], bv[j], acc[i][j]);
        }
        __syncthreads();
    }
    float* P = g_part + (size_t)(ks * B_DIM + b) * 16384;
#pragma unroll
    for (int i = 0; i < 8; i++)
#pragma unroll
        for (int j = 0; j < 8; j += 4)
            *(float4*)&P[(ty * 8 + i) * 128 + tx * 8 + j] =
                make_float4(acc[i][j], acc[i][j + 1], acc[i][j + 2], acc[i][j + 3]);
}

// ---------------------------------------------------------------------------
// K2: C = alpha*I + 2*gamma*G; register-resident Gauss-Jordan inverse.
// Writes (2*gamma*C^-1)*QSCALE split to fp16 hi/lo, then raises g_qflag[b].
// (C symmetric SPD -> Q symmetric, so row-major store serves as [s][r] too.)
// ---------------------------------------------------------------------------
__global__ void __launch_bounds__(1024, 1) k2_inv(const float* __restrict__ alpha,
                                                  const float* __restrict__ gamma) {
    __shared__ float s_rowk[2][128];
    __shared__ float s_colk[2][128];
    __shared__ float s_invp[2];

    int b = blockIdx.x;
    int t = threadIdx.x;
    int i  = t >> 3;
    int jc = (t & 7) << 4;
    float a  = alpha[b];
    float g2 = 2.0f * gamma[b];

    float M[16];
#pragma unroll
    for (int q = 0; q < 16; q++) {
        int e = i * 128 + jc + q;
        float s = 0.f;
#pragma unroll
        for (int p = 0; p < KSPLIT; p++)
            s += g_part[((size_t)(p * B_DIM + b)) * 16384 + e];
        M[q] = g2 * s + ((jc + q) == i ? a : 0.f);
    }
    if (i == 0) {
#pragma unroll
        for (int q = 0; q < 16; q++) s_rowk[0][jc + q] = M[q];
        if (jc == 0) s_invp[0] = 1.0f / M[0];
    }
    if (jc == 0) s_colk[0][i] = M[0];
    __syncthreads();

    for (int k = 0; k < 128; k++) {
        int par = k & 1;
        float ip = s_invp[par];
        if (i == k) {
#pragma unroll
            for (int q = 0; q < 16; q++) M[q] *= ip;
            if (k >= jc && k < jc + 16) M[k - jc] = ip;
        } else {
            float c = s_colk[par][i] * ip;
#pragma unroll
            for (int q = 0; q < 16; q++)
                M[q] = fmaf(-c, s_rowk[par][jc + q], M[q]);
            if (k >= jc && k < jc + 16) M[k - jc] = -c;
        }
        int kn = k + 1;
        if (kn < 128) {
            int pn = kn & 1;
            if (i == kn) {
#pragma unroll
                for (int q = 0; q < 16; q++) s_rowk[pn][jc + q] = M[q];
                if (kn >= jc && kn < jc + 16) s_invp[pn] = 1.0f / M[kn - jc];
            }
            if (kn >= jc && kn < jc + 16) s_colk[pn][i] = M[kn - jc];
        }
        __syncthreads();
    }

    __half* Qh = g_Qh + (size_t)b * 16384;
    __half* Ql = g_Ql + (size_t)b * 16384;
    float g2s = g2 * QSCALE;
#pragma unroll
    for (int q = 0; q < 16; q++) {
        float v = g2s * M[q];
        __half h = __float2half_rn(v);
        __half l = __float2half_rn(v - __half2float(h));
        Qh[i * 128 + jc + q] = h;
        Ql[i * 128 + jc + q] = l;
    }

    __syncthreads();
    if (t == 0) {
        __threadfence();
        atomicExch(&g_qflag[b], 1);
    }
}

// ---------------------------------------------------------------------------
// K4: fused  AN = A @ N^T  (fp16 2-way split, 3x HMMA, fp32 acc)
//            out = AN @ Q  (HMMA epilogue: acc+Q split to fp16, 3-term, /QSCALE)
// ---------------------------------------------------------------------------
#define BM 256
#define BK 32
#define NTHREADS 512
#define RS 40                          // halves per smem row (80B, 16B-aligned)
#define ASTG (512 * RS)                // halves per A stage (256 rows hi + lo)
#define A_LO_B (256 * RS * 2)          // byte offset of A-lo inside stage
#define BOFF (2 * ASTG)                // halves: start of B region
#define BSTG (256 * RS)                // halves per B stage (128 rows hi + lo)
#define B_LO_B (128 * RS * 2)          // byte offset of B-lo inside stage
#define K4_SMEM ((2 * ASTG + 3 * BSTG) * 2)   // 143360 bytes

// Epilogue smem layout (reuses pipeline smem): row stride 272 B (136 halves)
#define ERS 272
#define E_AH 0                         // AN hi: 128 rows x 272B = 34816
#define E_AL 34816                     // AN lo
#define E_QH 69632                     // Q hi:  128 rows x 272B
#define E_QL 104448                    // Q lo   (end 139264 <= 143360)

__device__ __forceinline__ uint32_t smem_u32(const void* p) {
    return (uint32_t)__cvta_generic_to_shared(p);
}
__device__ __forceinline__ void cp_async16(uint32_t saddr, const void* g) {
    asm volatile("cp.async.cg.shared.global [%0], [%1], 16;" :: "r"(saddr), "l"(g) : "memory");
}
__device__ __forceinline__ void ldsm_x4(uint32_t addr, uint32_t& r0, uint32_t& r1,
                                        uint32_t& r2, uint32_t& r3) {
    asm volatile("ldmatrix.sync.aligned.m8n8.x4.shared.b16 {%0,%1,%2,%3}, [%4];"
                 : "=r"(r0), "=r"(r1), "=r"(r2), "=r"(r3) : "r"(addr));
}
__device__ __forceinline__ void mma_f16(float* d, const uint32_t* a, const uint32_t* b) {
    asm volatile(
        "mma.sync.aligned.m16n8k16.row.col.f32.f16.f16.f32 "
        "{%0,%1,%2,%3}, {%4,%5,%6,%7}, {%8,%9}, {%0,%1,%2,%3};"
        : "+f"(d[0]), "+f"(d[1]), "+f"(d[2]), "+f"(d[3])
        : "r"(a[0]), "r"(a[1]), "r"(a[2]), "r"(a[3]),
          "r"(b[0]), "r"(b[1]));
}
__device__ __forceinline__ uint32_t pack_hi(float x, float y) {
    __half2 h = __halves2half2(__float2half_rn(x), __float2half_rn(y));
    return *(uint32_t*)&h;
}
__device__ __forceinline__ uint32_t pack_lo(float x, float y) {
    __half hx = __float2half_rn(x), hy = __float2half_rn(y);
    __half2 l = __halves2half2(__float2half_rn(x - __half2float(hx)),
                               __float2half_rn(y - __half2float(hy)));
    return *(uint32_t*)&l;
}

__global__ void __launch_bounds__(NTHREADS, 1) k4_fused(const float* __restrict__ A,
                                                        float* __restrict__ O) {
    extern __shared__ __half smh[];
    uint32_t sb = smem_u32(smh);
    int b  = blockIdx.y;
    int m0 = blockIdx.x * BM;
    int tid = threadIdx.x;
    int lane = tid & 31, wid = tid >> 5;
    int wm = wid & 3;        // 4 warps in M -> 64 rows each
    int wn = wid >> 2;       // 4 warps in N -> 32 cols each

    const float*  Ab  = A + (size_t)b * H_DIM * W_DIM;
    const __half* Bhg = g_Nh + (size_t)b * R_DIM * W_DIM;
    const __half* Blg = g_Nl + (size_t)b * R_DIM * W_DIM;

    float acc[4][4][4];
#pragma unroll
    for (int mt = 0; mt < 4; mt++)
#pragma unroll
        for (int nt = 0; nt < 4; nt++)
#pragma unroll
            for (int r = 0; r < 4; r++) acc[mt][nt][r] = 0.f;

    float4 a4[4];
    int brow = tid >> 2, bcol = tid & 3;

    auto ldg_A = [&](int kk) {
#pragma unroll
        for (int i = 0; i < 4; i++) {
            int v = tid + i * NTHREADS;
            int row = v >> 3, kc = v & 7;
            a4[i] = *(const float4*)(Ab + (size_t)(m0 + row) * W_DIM + kk + kc * 4);
        }
    };
    auto cpb = [&](int st, int kk) {
        uint32_t bbase = sb + (BOFF + st * BSTG) * 2;
        uint32_t off = (uint32_t)(brow * RS + bcol * 8) * 2;
        cp_async16(bbase + off,          Bhg + (size_t)brow * W_DIM + kk + bcol * 8);
        cp_async16(bbase + B_LO_B + off, Blg + (size_t)brow * W_DIM + kk + bcol * 8);
        asm volatile("cp.async.commit_group;" ::: "memory");
    };
    auto sts_A = [&](int st) {
        uint32_t abase = sb + st * (ASTG * 2);
#pragma unroll
        for (int i = 0; i < 4; i += 2) {
            int v0i = tid + i * NTHREADS;
            int v1i = tid + (i + 1) * NTHREADS;
            int r0 = v0i >> 3, c0 = v0i & 7;
            int r1 = v1i >> 3, c1 = v1i & 7;
            uint32_t h0 = pack_hi(a4[i].x, a4[i].y),   h1 = pack_hi(a4[i].z, a4[i].w);
            uint32_t l0 = pack_lo(a4[i].x, a4[i].y),   l1 = pack_lo(a4[i].z, a4[i].w);
            uint32_t h2 = pack_hi(a4[i+1].x, a4[i+1].y), h3 = pack_hi(a4[i+1].z, a4[i+1].w);
            uint32_t l2 = pack_lo(a4[i+1].x, a4[i+1].y), l3 = pack_lo(a4[i+1].z, a4[i+1].w);
            uint32_t o0 = (uint32_t)(r0 * RS + c0 * 4) * 2;
            uint32_t o1 = (uint32_t)(r1 * RS + c1 * 4) * 2;
            asm volatile("st.shared.v2.b32 [%0], {%1,%2};"
                         :: "r"(abase + o0), "r"(h0), "r"(h1) : "memory");
            asm volatile("st.shared.v2.b32 [%0], {%1,%2};"
                         :: "r"(abase + A_LO_B + o0), "r"(l0), "r"(l1) : "memory");
            asm volatile("st.shared.v2.b32 [%0], {%1,%2};"
                         :: "r"(abase + o1), "r"(h2), "r"(h3) : "memory");
            asm volatile("st.shared.v2.b32 [%0], {%1,%2};"
                         :: "r"(abase + A_LO_B + o1), "r"(l2), "r"(l3) : "memory");
        }
    };

    ldg_A(0);
    cpb(0, 0);
    cpb(1, BK);

    const int KITERS = W_DIM / BK; // 128
    for (int kb = 0; kb < KITERS; kb++) {
        sts_A(kb & 1);
        if (kb + 1 < KITERS)
            asm volatile("cp.async.wait_group 1;" ::: "memory");
        else
            asm volatile("cp.async.wait_group 0;" ::: "memory");
        __syncthreads();
        if (kb + 1 < KITERS) ldg_A((kb + 1) * BK);
        if (kb + 2 < KITERS) cpb((kb + 2) % 3, (kb + 2) * BK);

        uint32_t abase = sb + (kb & 1) * (ASTG * 2);
        uint32_t bbase = sb + (BOFF + (kb % 3) * BSTG) * 2;

#pragma unroll
        for (int ks = 0; ks < 2; ks++) {
            uint32_t bhi[4][2], blo[4][2];
            int idx = lane >> 3;
            int kboff = ks * 32 + (idx & 1) * 16;
#pragma unroll
            for (int h = 0; h < 2; h++) {
                int nrow = wn * 32 + h * 16 + (idx >> 1) * 8 + (lane & 7);
                uint32_t r0, r1, r2, r3;
                ldsm_x4(bbase + nrow * (RS * 2) + kboff, r0, r1, r2, r3);
                bhi[2 * h][0] = r0; bhi[2 * h][1] = r1;
                bhi[2 * h + 1][0] = r2; bhi[2 * h + 1][1] = r3;
                ldsm_x4(bbase + B_LO_B + nrow * (RS * 2) + kboff, r0, r1, r2, r3);
                blo[2 * h][0] = r0; blo[2 * h][1] = r1;
                blo[2 * h + 1][0] = r2; blo[2 * h + 1][1] = r3;
            }
            int karow = ks * 32 + (lane >> 4) * 16;
#pragma unroll
            for (int mt = 0; mt < 4; mt++) {
                int arow = wm * 64 + mt * 16 + (lane & 15);
                uint32_t ah[4], al[4];
                ldsm_x4(abase + arow * (RS * 2) + karow, ah[0], ah[1], ah[2], ah[3]);
                ldsm_x4(abase + A_LO_B + arow * (RS * 2) + karow, al[0], al[1], al[2], al[3]);
#pragma unroll
                for (int nt = 0; nt < 4; nt++) mma_f16(acc[mt][nt], al, bhi[nt]);
#pragma unroll
                for (int nt = 0; nt < 4; nt++) mma_f16(acc[mt][nt], ah, blo[nt]);
#pragma unroll
                for (int nt = 0; nt < 4; nt++) mma_f16(acc[mt][nt], ah, bhi[nt]);
            }
        }
    }

    // ===== HMMA epilogue: out = (acc @ Qscaled) / QSCALE =====
    if (tid == 0) {
        while (((volatile int*)g_qflag)[b] == 0) __nanosleep(64);
    }
    __syncthreads();
    __threadfence();

    // load Q hi/lo into smem ([s][r], symmetric so row-major read is fine)
    {
        const __half* Qhg = g_Qh + (size_t)b * 16384;
        const __half* Qlg = g_Ql + (size_t)b * 16384;
#pragma unroll
        for (int i = 0; i < 4; i++) {
            int u = tid + i * NTHREADS;      // 2048 chunks of 8 halves
            int row = u >> 4, seg = u & 15;
            uint4 vh = *(const uint4*)(Qhg + row * 128 + seg * 8);
            uint4 vl = *(const uint4*)(Qlg + row * 128 + seg * 8);
            asm volatile("st.shared.v4.b32 [%0], {%1,%2,%3,%4};"
                         :: "r"(sb + E_QH + row * ERS + seg * 16),
                            "r"(vh.x), "r"(vh.y), "r"(vh.z), "r"(vh.w) : "memory");
            asm volatile("st.shared.v4.b32 [%0], {%1,%2,%3,%4};"
                         :: "r"(sb + E_QL + row * ERS + seg * 16),
                            "r"(vl.x), "r"(vl.y), "r"(vl.z), "r"(vl.w) : "memory");
        }
    }

    int wmE = wid & 3;       // 4 groups of 32 h-rows
    int wnE = wid >> 2;      // 4 groups of 32 s-cols
    const float qinv = 1.0f / QSCALE;

#pragma unroll
    for (int half = 0; half < 2; half++) {
        __syncthreads();
        // warps owning this h-half store their acc (split hi/lo) as A-operand
        if ((wm >> 1) == half) {
            int wml = wm & 1;
#pragma unroll
            for (int mt = 0; mt < 4; mt++)
#pragma unroll
                for (int nt = 0; nt < 4; nt++) {
                    int h = wml * 64 + mt * 16 + (lane >> 2);
                    int c = wn * 32 + nt * 8 + (lane & 3) * 2;
                    uint32_t hi01 = pack_hi(acc[mt][nt][0], acc[mt][nt][1]);
                    uint32_t lo01 = pack_lo(acc[mt][nt][0], acc[mt][nt][1]);
                    uint32_t hi23 = pack_hi(acc[mt][nt][2], acc[mt][nt][3]);
                    uint32_t lo23 = pack_lo(acc[mt][nt][2], acc[mt][nt][3]);
                    uint32_t o = (uint32_t)(h * ERS + c * 2);
                    asm volatile("st.shared.b32 [%0], %1;" :: "r"(sb + E_AH + o), "r"(hi01) : "memory");
                    asm volatile("st.shared.b32 [%0], %1;" :: "r"(sb + E_AL + o), "r"(lo01) : "memory");
                    uint32_t o8 = o + 8 * ERS;
                    asm volatile("st.shared.b32 [%0], %1;" :: "r"(sb + E_AH + o8), "r"(hi23) : "memory");
                    asm volatile("st.shared.b32 [%0], %1;" :: "r"(sb + E_AL + o8), "r"(lo23) : "memory");
                }
        }
        __syncthreads();

        float outr[2][4][4];
#pragma unroll
        for (int mtE = 0; mtE < 2; mtE++)
#pragma unroll
            for (int nt = 0; nt < 4; nt++)
#pragma unroll
                for (int r = 0; r < 4; r++) outr[mtE][nt][r] = 0.f;

#pragma unroll
        for (int ks = 0; ks < 8; ks++) {
            uint32_t bhi[4][2], blo[4][2];
            int idx = lane >> 3;
            int kboff = ks * 32 + (idx & 1) * 16;
#pragma unroll
            for (int h2 = 0; h2 < 2; h2++) {
                int nrow = wnE * 32 + h2 * 16 + (idx >> 1) * 8 + (lane & 7);
                uint32_t r0, r1, r2, r3;
                ldsm_x4(sb + E_QH + nrow * ERS + kboff, r0, r1, r2, r3);
                bhi[2 * h2][0] = r0; bhi[2 * h2][1] = r1;
                bhi[2 * h2 + 1][0] = r2; bhi[2 * h2 + 1][1] = r3;
                ldsm_x4(sb + E_QL + nrow * ERS + kboff, r0, r1, r2, r3);
                blo[2 * h2][0] = r0; blo[2 * h2][1] = r1;
                blo[2 * h2 + 1][0] = r2; blo[2 * h2 + 1][1] = r3;
            }
            int karow = ks * 32 + (lane >> 4) * 16;
#pragma unroll
            for (int mtE = 0; mtE < 2; mtE++) {
                int arow = wmE * 32 + mtE * 16 + (lane & 15);
                uint32_t ah[4], al[4];
                ldsm_x4(sb + E_AH + arow * ERS + karow, ah[0], ah[1], ah[2], ah[3]);
                ldsm_x4(sb + E_AL + arow * ERS + karow, al[0], al[1], al[2], al[3]);
#pragma unroll
                for (int nt = 0; nt < 4; nt++) mma_f16(outr[mtE][nt], al, bhi[nt]);
#pragma unroll
                for (int nt = 0; nt < 4; nt++) mma_f16(outr[mtE][nt], ah, blo[nt]);
#pragma unroll
                for (int nt = 0; nt < 4; nt++) mma_f16(outr[mtE][nt], ah, bhi[nt]);
            }
        }

#pragma unroll
        for (int mtE = 0; mtE < 2; mtE++)
#pragma unroll
            for (int nt = 0; nt < 4; nt++) {
                int hg = m0 + half * 128 + wmE * 32 + mtE * 16 + (lane >> 2);
                int c  = wnE * 32 + nt * 8 + (lane & 3) * 2;
                float2 v0 = make_float2(outr[mtE][nt][0] * qinv, outr[mtE][nt][1] * qinv);
                float2 v1 = make_float2(outr[mtE][nt][2] * qinv, outr[mtE][nt][3] * qinv);
                *(float2*)(O + ((size_t)b * H_DIM + hg) * R_DIM + c)     = v0;
                *(float2*)(O + ((size_t)b * H_DIM + hg + 8) * R_DIM + c) = v1;
            }
    }
}

// ---------------------------------------------------------------------------
// Fork/join stream resources, created once at load.
// ---------------------------------------------------------------------------
namespace {
struct AuxStreams {
    cudaStream_t s2 = nullptr;
    cudaEvent_t  evA = nullptr, evB = nullptr;
    bool ok = false;
    AuxStreams() {
        ok = (cudaStreamCreateWithFlags(&s2, cudaStreamNonBlocking) == cudaSuccess) &&
             (cudaEventCreateWithFlags(&evA, cudaEventDisableTiming) == cudaSuccess) &&
             (cudaEventCreateWithFlags(&evB, cudaEventDisableTiming) == cudaSuccess);
    }
};
AuxStreams g_aux;
}

extern "C" void kernel_launch(void* const* d_in, const int* in_sizes, int n_in,
                              void* d_out, int out_size) {
    (void)in_sizes; (void)n_in; (void)out_size;
    const float* N     = (const float*)d_in[0];
    const float* A     = (const float*)d_in[1];
    const float* alpha = (const float*)d_in[2];
    const float* gamma = (const float*)d_in[3];
    float* out = (float*)d_out;

    cudaFuncSetAttribute(k4_fused, cudaFuncAttributeMaxDynamicSharedMemorySize, K4_SMEM);

    dim3 g1(KSPLIT, B_DIM);
    if (g_aux.ok) {
        cudaEventRecord(g_aux.evA, 0);
        cudaStreamWaitEvent(g_aux.s2, g_aux.evA, 0);
        k1_gram<<<g1, 256, 0, g_aux.s2>>>(N);
        k2_inv<<<B_DIM, 1024, 0, g_aux.s2>>>(alpha, gamma);
    } else {
        k1_gram<<<g1, 256>>>(N);
        k2_inv<<<B_DIM, 1024>>>(alpha, gamma);
    }

    k0_split<<<(B_DIM * R_DIM * W_DIM) / 1024, 256>>>(N);
    dim3 g4(H_DIM / BM, B_DIM);   // 16 x 8 = 128 CTAs, one wave
    k4_fused<<<g4, NTHREADS, K4_SMEM>>>(A, out);

    if (g_aux.ok) {
        cudaEventRecord(g_aux.evB, g_aux.s2);
        cudaStreamWaitEvent(0, g_aux.evB, 0);
    }
}